// round 4
// baseline (speedup 1.0000x reference)
#include <cuda_runtime.h>
#include <math.h>

#define BATCH  64
#define LSUB   512
#define SWORDS 512
#define HID    768
#define NC     9
#define NWORDS (BATCH * SWORDS)
#define NBLK   1024         // 16 blocks per batch, 32 words (16 pairs) per block

typedef unsigned long long u64;

__device__ float g_ploss[NBLK];
__device__ int   g_pcnt[NBLK];

__device__ __forceinline__ u64 fma2(u64 a, u64 b, u64 c) {
    u64 d; asm("fma.rn.f32x2 %0,%1,%2,%3;" : "=l"(d) : "l"(a), "l"(b), "l"(c)); return d;
}
__device__ __forceinline__ u64 add2(u64 a, u64 b) {
    u64 d; asm("add.rn.f32x2 %0,%1,%2;" : "=l"(d) : "l"(a), "l"(b)); return d;
}
__device__ __forceinline__ float upk_sum(u64 v) {
    float lo, hi; asm("mov.b64 {%0,%1},%2;" : "=f"(lo), "=f"(hi) : "l"(v)); return lo + hi;
}

// ---------------------------------------------------------------------------
// Main kernel: 1024 blocks x 256 threads. Block b owns words
// [batch*512 + seg*32, +32), batch=b>>4, seg=b&15. Block re-scans its batch's
// ids_lens in shared (shfl scan), then 8 warps each process 2 word-pairs with
// packed f32x2 math against W transposed in shared.
// ---------------------------------------------------------------------------
__global__ void __launch_bounds__(256) main_kernel(
    const float* __restrict__ x,        // [B, L, H]
    const float* __restrict__ W,        // [H, C]
    const float* __restrict__ bias,     // [C]
    const int*   __restrict__ ids_lens, // [B, S]
    const int*   __restrict__ label_ids,
    float*       __restrict__ out)      // out[0]=loss, out[1..]=pred
{
    __shared__ float Ws[NC * HID];      // transposed: Ws[c*HID + h]
    __shared__ int   s_len[SWORDS];
    __shared__ int   s_start[SWORDS];
    __shared__ int   s_wsum[8];
    __shared__ float sb[NC];
    __shared__ float s_loss;
    __shared__ int   s_cnt;

    const int tid  = threadIdx.x;
    const int lane = tid & 31;
    const int warp = tid >> 5;
    const int blk  = blockIdx.x;
    const int batch = blk >> 4;
    const int seg   = blk & 15;

    // ---- W -> shared (transposed), bias, loss init ----
    for (int i = tid; i < HID * NC; i += 256) {
        int h = i / NC, c = i % NC;
        Ws[c * HID + h] = W[i];
    }
    if (tid < NC) sb[tid] = bias[tid];
    if (tid == 0) { s_loss = 0.0f; s_cnt = 0; }

    // ---- in-block scan of this batch's ids_lens (512 ints, 2 per thread) ----
    const int* Lb = ids_lens + batch * SWORDS;
    int2 lp = ((const int2*)Lb)[tid];              // words 2*tid, 2*tid+1
    int sum2 = lp.x + lp.y;
    int inc = sum2;
#pragma unroll
    for (int off = 1; off < 32; off <<= 1) {
        int n = __shfl_up_sync(0xffffffffu, inc, off);
        if (lane >= off) inc += n;
    }
    int lane_ex = inc - sum2;
    if (lane == 31) s_wsum[warp] = inc;
    __syncthreads();
    int wbase = 0;
#pragma unroll
    for (int i = 0; i < 8; i++) if (i < warp) wbase += s_wsum[i];
    int ex0 = wbase + lane_ex;
    s_len[2 * tid]       = lp.x;
    s_len[2 * tid + 1]   = lp.y;
    s_start[2 * tid]     = ex0;
    s_start[2 * tid + 1] = ex0 + lp.x;
    __syncthreads();

    float lloss = 0.0f;
    int   lcnt  = 0;

    const ulonglong2 z2 = make_ulonglong2(0ull, 0ull);
    const int RS = HID / 4;     // row stride in 16B ulonglong2 chunks = 192  (FIXED)

#pragma unroll
    for (int it = 0; it < 2; it++) {
        int pi  = warp + it * 8;                   // pair index within block (0..15)
        int wl0 = seg * 32 + 2 * pi;               // word index within batch
        int w0  = batch * SWORDS + wl0;
        int w1  = w0 + 1;
        int len0 = s_len[wl0],     len1 = s_len[wl0 + 1];
        int st0  = s_start[wl0],   st1  = s_start[wl0 + 1];

        const ulonglong2* base0 = (const ulonglong2*)(x + ((size_t)(batch * LSUB + st0)) * HID);
        const ulonglong2* base1 = (const ulonglong2*)(x + ((size_t)(batch * LSUB + st1)) * HID);

        u64 acc0[NC], acc1[NC];
#pragma unroll
        for (int c = 0; c < NC; c++) { acc0[c] = 0ull; acc1[c] = 0ull; }

#pragma unroll
        for (int g = 0; g < 6; g++) {
            int idx = g * 32 + lane;               // 16B-chunk index within row
            ulonglong2 a0 = (len0 > 0) ? base0[idx]          : z2;
            ulonglong2 a1 = (len0 > 1) ? base0[idx + RS]     : z2;
            ulonglong2 a2 = (len0 > 2) ? base0[idx + 2 * RS] : z2;
            ulonglong2 c0 = (len1 > 0) ? base1[idx]          : z2;
            ulonglong2 c1 = (len1 > 1) ? base1[idx + RS]     : z2;
            ulonglong2 c2 = (len1 > 2) ? base1[idx + 2 * RS] : z2;

            u64 v0l = add2(a0.x, add2(a1.x, a2.x));
            u64 v0h = add2(a0.y, add2(a1.y, a2.y));
            u64 v1l = add2(c0.x, add2(c1.x, c2.x));
            u64 v1h = add2(c0.y, add2(c1.y, c2.y));

            int hb = g * 128 + lane * 4;
#pragma unroll
            for (int c = 0; c < NC; c++) {
                ulonglong2 wc = *(const ulonglong2*)&Ws[c * HID + hb];
                acc0[c] = fma2(v0l, wc.x, acc0[c]);
                acc0[c] = fma2(v0h, wc.y, acc0[c]);
                acc1[c] = fma2(v1l, wc.x, acc1[c]);
                acc1[c] = fma2(v1h, wc.y, acc1[c]);
            }
        }

        // collapse packed halves, then warp tree-reduce 18 scalars
        float r0[NC], r1[NC];
#pragma unroll
        for (int c = 0; c < NC; c++) { r0[c] = upk_sum(acc0[c]); r1[c] = upk_sum(acc1[c]); }
#pragma unroll
        for (int c = 0; c < NC; c++) {
#pragma unroll
            for (int off = 16; off; off >>= 1) {
                r0[c] += __shfl_xor_sync(0xffffffffu, r0[c], off);
                r1[c] += __shfl_xor_sync(0xffffffffu, r1[c], off);
            }
        }

        if (lane == 0) {
#pragma unroll
            for (int which = 0; which < 2; which++) {
                int    w   = which ? w1 : w0;
                int    len = which ? len1 : len0;
                float* a   = which ? r1 : r0;

                float inv = (len > 0) ? (1.0f / (float)len) : 0.0f;
                float lg[NC];
                float m = -1e30f; int am = 0;
#pragma unroll
                for (int c = 0; c < NC; c++) {
                    lg[c] = fmaf(a[c], inv, sb[c]);
                    if (lg[c] > m) { m = lg[c]; am = c; }
                }
                out[1 + w] = (float)am;
                if (len > 0) {
                    float sum = 0.0f;
#pragma unroll
                    for (int c = 0; c < NC; c++) sum += __expf(lg[c] - m);
                    int lab = label_ids[w];
                    lab = lab < 0 ? 0 : (lab > NC - 1 ? NC - 1 : lab);
                    lloss += -(lg[lab] - m - __logf(sum));
                    lcnt  += 1;
                }
            }
        }
    }

    if (lane == 0 && lcnt > 0) {
        atomicAdd(&s_loss, lloss);
        atomicAdd(&s_cnt, lcnt);
    }
    __syncthreads();
    if (tid == 0) {                                 // every block writes its slot
        g_ploss[blk] = s_loss;
        g_pcnt[blk]  = s_cnt;
    }
}

// ---------------------------------------------------------------------------
// Finalize: reduce 1024 per-block partials. <<<1, 1024>>>
// ---------------------------------------------------------------------------
__global__ void finalize_kernel(float* __restrict__ out) {
    __shared__ float sl[32];
    __shared__ int   sc[32];
    int t = threadIdx.x, lane = t & 31, warp = t >> 5;
    float v = g_ploss[t];
    int   c = g_pcnt[t];
#pragma unroll
    for (int off = 16; off; off >>= 1) {
        v += __shfl_xor_sync(0xffffffffu, v, off);
        c += __shfl_xor_sync(0xffffffffu, c, off);
    }
    if (lane == 0) { sl[warp] = v; sc[warp] = c; }
    __syncthreads();
    if (warp == 0) {
        float vv = sl[lane];
        int   cc = sc[lane];
#pragma unroll
        for (int off = 16; off; off >>= 1) {
            vv += __shfl_xor_sync(0xffffffffu, vv, off);
            cc += __shfl_xor_sync(0xffffffffu, cc, off);
        }
        if (lane == 0) out[0] = vv / fmaxf((float)cc, 1.0f);
    }
}

extern "C" void kernel_launch(void* const* d_in, const int* in_sizes, int n_in,
                              void* d_out, int out_size) {
    const float* bert_out  = (const float*)d_in[0];
    const float* W         = (const float*)d_in[1];
    const float* b         = (const float*)d_in[2];
    const int*   ids_lens  = (const int*)d_in[4];
    const int*   label_ids = (const int*)d_in[5];
    float* out = (float*)d_out;

    main_kernel<<<NBLK, 256>>>(bert_out, W, b, ids_lens, label_ids, out);
    finalize_kernel<<<1, 1024>>>(out);
}